// round 15
// baseline (speedup 1.0000x reference)
#include <cuda_runtime.h>
#include <math.h>

#define D_DET   363
#define N_ANG   360
#define QTR_A   90
#define IMG     256
#define PAD     76
#define SROW    544                    // padded row length (float4 pack entries)

// Packed, zero-padded filtered sinogram:
// g_pack[angle*SROW + i] = (fA[i], fA[i+1]-fA[i], fB[i], fB[i+1]-fB[i])
__device__ float4 g_pack[N_ANG * SROW];
// Ramp impulse-response table: g_h2[j+4] = h[(j-362) mod 363], zeros at edges
__device__ float  g_h2[736];
// Partial backprojection sums: [batch*4 + quarter][pixel]
__device__ float  g_part[8][IMG * IMG];

// ============================================================================
// Kernel 0: prep — 736-entry h table, computed once.
// h[n] = (182 cos(362 n pi/363) - 181 cos(364 n pi/363) - 1) / (363^2 sin^2(n pi/363))
// ============================================================================
__global__ __launch_bounds__(128) void prep_kernel() {
    int i = blockIdx.x * 128 + threadIdx.x;
    if (i >= 736) return;
    float v = 0.0f;
    int jj = i - 4;
    if (jj >= 0 && jj <= 724) {
        int n = (jj >= 362) ? (jj - 362) : (jj + 1);   // (jj-362) mod 363
        if (n == 0) {
            v = 2.0f * 181.0f * 182.0f / (363.0f * 363.0f);
        } else {
            int r1 = (362 * n) % 726;                  // exact mod-2pi reduction
            int r2 = (364 * n) % 726;
            float c1 = cospif((float)r1 * (1.0f / 363.0f));
            float c2 = cospif((float)r2 * (1.0f / 363.0f));
            float s  = sinpif((float)n  * (1.0f / 363.0f));
            v = (182.0f * c1 - 181.0f * c2 - 1.0f) / (363.0f * 363.0f * s * s);
        }
    }
    g_h2[i] = v;
}

// ============================================================================
// Kernel 1: ramp filter. One block per ANGLE (384 threads): threads 0-181
// convolve batch A's row, 192-373 batch B's row (R13-proven conv core),
// then write the packed float4 row for bp's single-LDG.128 inner loop.
// ============================================================================
__global__ __launch_bounds__(384) void filter_kernel(const float* __restrict__ sino) {
    __shared__ float2 s_h2p[368];      // 736 floats
    __shared__ float2 s_row2[2][184];  // 368 floats each; [363..367] = 0
    __shared__ float  s_out[2][546];   // padded rows (zeros in pads)
    float* s_h2 = (float*)s_h2p;

    int t   = threadIdx.x;             // 0..383
    int ang = blockIdx.x;              // 0..359

    if (t < 184)
        ((float4*)s_h2)[t] = ((const float4*)g_h2)[t];
    for (int i = t; i < 736; i += 384) {
        int r = i / 368, c = i - r * 368;                    // r: 0=batchA, 1=batchB
        ((float*)s_row2)[i] = (c < D_DET) ? __ldg(sino + (ang + r * N_ANG) * D_DET + c) : 0.0f;
    }
    for (int i = t; i < 2 * 546; i += 384) ((float*)s_out)[i] = 0.0f;
    __syncthreads();

    // ---- convolution: outputs d0, d0+1; h window slides 2 per double-step ----
    int wg = t / 192;                  // 0 -> batch A, 1 -> batch B
    int j  = t - wg * 192;
    if (j < 182) {
        int d0   = 2 * j;                        // 0..362
        int base = 366 + d0;                     // even -> float2-aligned pairs
        float w0 = s_h2[base];
        float w1 = s_h2[base + 1];
        int hb2  = (base - 2) >> 1;              // float2 index of s_h2[base-2]
        const float2* sr = s_row2[wg];
        float a0 = 0.f, a1 = 0.f;
        #pragma unroll 4
        for (int k2 = 0; k2 < 182; k2++) {       // k = 2*k2, 2*k2+1 (row[363]=0)
            float2 sv = sr[k2];                  // broadcast across warp
            float2 hp = s_h2p[hb2 - k2];         // (h[base-2-2k2], h[base-1-2k2])
            a0 = fmaf(sv.x, w0, a0);
            a1 = fmaf(sv.x, w1, a1);
            a0 = fmaf(sv.y, hp.y, a0);
            a1 = fmaf(sv.y, w0, a1);
            w1 = hp.y; w0 = hp.x;
        }
        s_out[wg][PAD + d0] = a0;
        if (d0 + 1 < D_DET) s_out[wg][PAD + d0 + 1] = a1;
    }
    __syncthreads();

    // ---- write packed padded row: (fA, dA, fB, dB) ----
    for (int i = t; i < SROW; i += 384) {
        float vA = s_out[0][i];
        float vB = s_out[1][i];
        g_pack[ang * SROW + i] =
            make_float4(vA, s_out[0][i + 1] - vA, vB, s_out[1][i + 1] - vB);
    }
}

// ============================================================================
// Kernel 2: backprojection. 16x16 tile; z = angle quarter (90 angles/chain);
// both batches per thread via ONE LDG.128 per iteration. 8192 warps.
// ============================================================================
__global__ __launch_bounds__(256) void bp_kernel() {
    __shared__ float2 s_trig[QTR_A];
    int tid = threadIdx.y * 16 + threadIdx.x;
    int q = blockIdx.z;                // angle quarter
    int a0 = q * QTR_A;

    const float C1 = 32761.0f / (127.5f * 1.41421356237309515f);  // 181^2/(127.5*sqrt2)
    if (tid < QTR_A) {
        float sa, ca;
        sincospif((float)(a0 + tid) * (1.0f / 360.0f), &sa, &ca); // angle = idx*pi/360
        s_trig[tid] = make_float2(ca * C1, sa * C1);
    }
    __syncthreads();

    int x = blockIdx.x * 16 + threadIdx.x;
    int y = blockIdx.y * 16 + threadIdx.y;
    float xf = fmaf((float)x, 2.0f / 255.0f, -1.0f);
    float yf = fmaf((float)y, 2.0f / 255.0f, -1.0f);

    const float4* p = g_pack + a0 * SROW;
    float accA = 0.0f, accB = 0.0f;
    #pragma unroll 5
    for (int a = 0; a < QTR_A; a++) {
        float2 cs = s_trig[a];
        float u  = fmaf(xf, cs.x, fmaf(yf, cs.y, 257.0f));  // 257 = PAD + (D-1)/2
        int   i0 = __float2int_rd(u);                       // u > 0: exact floor
        float w  = u - (float)i0;
        float4 v = __ldg(p + i0);
        accA = fmaf(w, v.y, accA + v.x);                    // fA0 + w*(fA1-fA0)
        accB = fmaf(w, v.w, accB + v.z);                    // fB0 + w*(fB1-fB0)
        p += SROW;
    }

    g_part[q][y * IMG + x]     = accA;
    g_part[4 + q][y * IMG + x] = accB;
}

// ============================================================================
// Kernel 3: combine quarters + scale. float2 granularity, 65536 threads
// (2x the warps of the float4 version -> less latency exposure).
// ============================================================================
__global__ __launch_bounds__(256) void combine_kernel(float* __restrict__ out) {
    int i = blockIdx.x * 256 + threadIdx.x;          // 0..65535 (float2 index)
    int b = i >> 15;                                  // 32768 float2 per batch
    int p = i & 32767;
    const float2* g0 = (const float2*)g_part[b * 4 + 0];
    const float2* g1 = (const float2*)g_part[b * 4 + 1];
    const float2* g2 = (const float2*)g_part[b * 4 + 2];
    const float2* g3 = (const float2*)g_part[b * 4 + 3];
    float2 u0 = g0[p], u1 = g1[p], u2 = g2[p], u3 = g3[p];
    const float SC = (float)(M_PI / 360.0);
    float2 w;
    w.x = ((u0.x + u1.x) + (u2.x + u3.x)) * SC;
    w.y = ((u0.y + u1.y) + (u2.y + u3.y)) * SC;
    ((float2*)out)[i] = w;
}

// ============================================================================
extern "C" void kernel_launch(void* const* d_in, const int* in_sizes, int n_in,
                              void* d_out, int out_size) {
    const float* sino = (const float*)d_in[0];   // (2,1,360,363) float32
    float* out = (float*)d_out;                  // (2,1,256,256) float32

    prep_kernel<<<6, 128>>>();
    filter_kernel<<<N_ANG, 384>>>(sino);
    bp_kernel<<<dim3(IMG / 16, IMG / 16, 4), dim3(16, 16)>>>();
    combine_kernel<<<256, 256>>>(out);
}

// round 16
// speedup vs baseline: 1.0244x; 1.0244x over previous
#include <cuda_runtime.h>
#include <cuda_fp16.h>
#include <math.h>

#define D_DET   363
#define N_ANG   360
#define QTR_A   90
#define IMG     256
#define PAD     76
#define SROW    544                    // padded row length (packed entries)

// Half-packed, zero-padded filtered sinogram (8B per entry):
// g_packh[angle*SROW + i] = half4 (fA[i], fA[i+1]-fA[i], fB[i], fB[i+1]-fB[i])
__device__ uint2 g_packh[N_ANG * SROW];
// Ramp impulse-response table: g_h2[j+4] = h[(j-362) mod 363], zeros at edges
__device__ float g_h2[736];
// Partial backprojection sums: [batch*4 + quarter][pixel]
__device__ float g_part[8][IMG * IMG];

// ============================================================================
// Kernel 0: prep — 736-entry h table, computed once.
// h[n] = (182 cos(362 n pi/363) - 181 cos(364 n pi/363) - 1) / (363^2 sin^2(n pi/363))
// ============================================================================
__global__ __launch_bounds__(128) void prep_kernel() {
    int i = blockIdx.x * 128 + threadIdx.x;
    if (i >= 736) return;
    float v = 0.0f;
    int jj = i - 4;
    if (jj >= 0 && jj <= 724) {
        int n = (jj >= 362) ? (jj - 362) : (jj + 1);   // (jj-362) mod 363
        if (n == 0) {
            v = 2.0f * 181.0f * 182.0f / (363.0f * 363.0f);
        } else {
            int r1 = (362 * n) % 726;                  // exact mod-2pi reduction
            int r2 = (364 * n) % 726;
            float c1 = cospif((float)r1 * (1.0f / 363.0f));
            float c2 = cospif((float)r2 * (1.0f / 363.0f));
            float s  = sinpif((float)n  * (1.0f / 363.0f));
            v = (182.0f * c1 - 181.0f * c2 - 1.0f) / (363.0f * 363.0f * s * s);
        }
    }
    g_h2[i] = v;
}

// ============================================================================
// Kernel 1: ramp filter. One block per ANGLE (384 threads): threads 0-181
// convolve batch A's row, 192-373 batch B's row (R13-proven conv core),
// then write the half-packed row (fA, dA, fB, dB) for bp's single LDG.64.
// ============================================================================
__global__ __launch_bounds__(384) void filter_kernel(const float* __restrict__ sino) {
    __shared__ float2 s_h2p[368];      // 736 floats
    __shared__ float2 s_row2[2][184];  // 368 floats each; [363..367] = 0
    __shared__ float  s_out[2][546];   // padded rows (zeros in pads)
    float* s_h2 = (float*)s_h2p;

    int t   = threadIdx.x;             // 0..383
    int ang = blockIdx.x;              // 0..359

    if (t < 184)
        ((float4*)s_h2)[t] = ((const float4*)g_h2)[t];
    for (int i = t; i < 736; i += 384) {
        int r = i / 368, c = i - r * 368;                    // r: 0=batchA, 1=batchB
        ((float*)s_row2)[i] = (c < D_DET) ? __ldg(sino + (ang + r * N_ANG) * D_DET + c) : 0.0f;
    }
    for (int i = t; i < 2 * 546; i += 384) ((float*)s_out)[i] = 0.0f;
    __syncthreads();

    // ---- convolution: outputs d0, d0+1; h window slides 2 per double-step ----
    int wg = t / 192;                  // 0 -> batch A, 1 -> batch B
    int j  = t - wg * 192;
    if (j < 182) {
        int d0   = 2 * j;                        // 0..362
        int base = 366 + d0;                     // even -> float2-aligned pairs
        float w0 = s_h2[base];
        float w1 = s_h2[base + 1];
        int hb2  = (base - 2) >> 1;              // float2 index of s_h2[base-2]
        const float2* sr = s_row2[wg];
        float a0 = 0.f, a1 = 0.f;
        #pragma unroll 4
        for (int k2 = 0; k2 < 182; k2++) {       // k = 2*k2, 2*k2+1 (row[363]=0)
            float2 sv = sr[k2];                  // broadcast across warp
            float2 hp = s_h2p[hb2 - k2];         // (h[base-2-2k2], h[base-1-2k2])
            a0 = fmaf(sv.x, w0, a0);
            a1 = fmaf(sv.x, w1, a1);
            a0 = fmaf(sv.y, hp.y, a0);
            a1 = fmaf(sv.y, w0, a1);
            w1 = hp.y; w0 = hp.x;
        }
        s_out[wg][PAD + d0] = a0;
        if (d0 + 1 < D_DET) s_out[wg][PAD + d0 + 1] = a1;
    }
    __syncthreads();

    // ---- write half-packed padded row: (fA, dA, fB, dB) as 4x fp16 ----
    for (int i = t; i < SROW; i += 384) {
        float vA = s_out[0][i];
        float vB = s_out[1][i];
        __half2 hA = __floats2half2_rn(vA, s_out[0][i + 1] - vA);
        __half2 hB = __floats2half2_rn(vB, s_out[1][i + 1] - vB);
        uint2 pk;
        pk.x = *reinterpret_cast<unsigned*>(&hA);
        pk.y = *reinterpret_cast<unsigned*>(&hB);
        g_packh[ang * SROW + i] = pk;
    }
}

// ============================================================================
// Kernel 2: backprojection. 16x16 tile; z = angle quarter (90 angles/chain);
// both batches per thread via ONE LDG.64 of 4 halves. 8192 warps (~55/SM).
// Weight w stays fp32; only the table values are fp16.
// ============================================================================
__global__ __launch_bounds__(256) void bp_kernel() {
    __shared__ float2 s_trig[QTR_A];
    int tid = threadIdx.y * 16 + threadIdx.x;
    int q = blockIdx.z;                // angle quarter
    int a0 = q * QTR_A;

    const float C1 = 32761.0f / (127.5f * 1.41421356237309515f);  // 181^2/(127.5*sqrt2)
    if (tid < QTR_A) {
        float sa, ca;
        sincospif((float)(a0 + tid) * (1.0f / 360.0f), &sa, &ca); // angle = idx*pi/360
        s_trig[tid] = make_float2(ca * C1, sa * C1);
    }
    __syncthreads();

    int x = blockIdx.x * 16 + threadIdx.x;
    int y = blockIdx.y * 16 + threadIdx.y;
    float xf = fmaf((float)x, 2.0f / 255.0f, -1.0f);
    float yf = fmaf((float)y, 2.0f / 255.0f, -1.0f);

    const uint2* p = g_packh + a0 * SROW;
    float accA = 0.0f, accB = 0.0f;
    #pragma unroll 5
    for (int a = 0; a < QTR_A; a++) {
        float2 cs = s_trig[a];
        float u  = fmaf(xf, cs.x, fmaf(yf, cs.y, 257.0f));  // 257 = PAD + (D-1)/2
        int   i0 = __float2int_rd(u);                       // u > 0: exact floor
        float w  = u - (float)i0;
        uint2 raw = __ldg(p + i0);
        float2 fA = __half22float2(*reinterpret_cast<__half2*>(&raw.x));
        float2 fB = __half22float2(*reinterpret_cast<__half2*>(&raw.y));
        accA = fmaf(w, fA.y, accA + fA.x);                  // fA0 + w*(fA1-fA0)
        accB = fmaf(w, fB.y, accB + fB.x);
        p += SROW;
    }

    g_part[q][y * IMG + x]     = accA;
    g_part[4 + q][y * IMG + x] = accB;
}

// ============================================================================
// Kernel 3: combine quarters + scale (R14-proven: 128 blocks, float4).
// ============================================================================
__global__ __launch_bounds__(256) void combine_kernel(float* __restrict__ out) {
    int i = blockIdx.x * 256 + threadIdx.x;          // 0..32767 (float4 index)
    int b = i >> 14;                                  // 16384 float4 per batch
    int p = i & 16383;
    const float4* g0 = (const float4*)g_part[b * 4 + 0];
    const float4* g1 = (const float4*)g_part[b * 4 + 1];
    const float4* g2 = (const float4*)g_part[b * 4 + 2];
    const float4* g3 = (const float4*)g_part[b * 4 + 3];
    float4 u0 = g0[p], u1 = g1[p], u2 = g2[p], u3 = g3[p];
    const float SC = (float)(M_PI / 360.0);
    float4 w;
    w.x = ((u0.x + u1.x) + (u2.x + u3.x)) * SC;
    w.y = ((u0.y + u1.y) + (u2.y + u3.y)) * SC;
    w.z = ((u0.z + u1.z) + (u2.z + u3.z)) * SC;
    w.w = ((u0.w + u1.w) + (u2.w + u3.w)) * SC;
    ((float4*)out)[i] = w;
}

// ============================================================================
extern "C" void kernel_launch(void* const* d_in, const int* in_sizes, int n_in,
                              void* d_out, int out_size) {
    const float* sino = (const float*)d_in[0];   // (2,1,360,363) float32
    float* out = (float*)d_out;                  // (2,1,256,256) float32

    prep_kernel<<<6, 128>>>();
    filter_kernel<<<N_ANG, 384>>>(sino);
    bp_kernel<<<dim3(IMG / 16, IMG / 16, 4), dim3(16, 16)>>>();
    combine_kernel<<<128, 256>>>(out);
}

// round 17
// speedup vs baseline: 1.0576x; 1.0325x over previous
#include <cuda_runtime.h>
#include <math.h>

#define D_DET   363
#define N_ANG   360
#define QTR_A   90
#define IMG     256
#define PAD     76
#define SROW    544                    // padded row length (float2 pairs)
#define NROWS   720                    // B * N_ANG
#define BATCH_OFF (N_ANG * SROW)       // float2 elements between batch 0 and batch 1

// Delta-packed, zero-padded, pre-scaled filtered sinogram:
// g_filt2[row][i] = (SC*f[i], SC*(f[i+1]-f[i])),  SC = pi/360
__device__ float2 g_filt2[NROWS * SROW];
// Ramp impulse-response table: g_h2[j+4] = h[(j-362) mod 363], zeros at edges
__device__ float  g_h2[736];

// ============================================================================
// Kernel 0: prep — 736-entry h table (computed once) + zero d_out for the
// backprojection's atomic accumulation. 128 blocks x 256 threads.
// h[n] = (182 cos(362 n pi/363) - 181 cos(364 n pi/363) - 1) / (363^2 sin^2(n pi/363))
// ============================================================================
__global__ __launch_bounds__(256) void prep_kernel(float* __restrict__ out) {
    int gid = blockIdx.x * 256 + threadIdx.x;        // 0..32767

    // zero the output (2*256*256 floats = 32768 float4)
    ((float4*)out)[gid] = make_float4(0.f, 0.f, 0.f, 0.f);

    if (gid < 736) {
        float v = 0.0f;
        int jj = gid - 4;
        if (jj >= 0 && jj <= 724) {
            int n = (jj >= 362) ? (jj - 362) : (jj + 1);   // (jj-362) mod 363
            if (n == 0) {
                v = 2.0f * 181.0f * 182.0f / (363.0f * 363.0f);
            } else {
                int r1 = (362 * n) % 726;                  // exact mod-2pi reduction
                int r2 = (364 * n) % 726;
                float c1 = cospif((float)r1 * (1.0f / 363.0f));
                float c2 = cospif((float)r2 * (1.0f / 363.0f));
                float s  = sinpif((float)n  * (1.0f / 363.0f));
                v = (182.0f * c1 - 181.0f * c2 - 1.0f) / (363.0f * 363.0f * s * s);
            }
        }
        g_h2[gid] = v;
    }
}

// ============================================================================
// Kernel 1: ramp filter (R14-proven form). 1 row/block, 2 outputs/thread,
// float2 LDS conv core; h table loaded from global. Output pre-scaled by
// pi/360 and delta-packed.
// ============================================================================
__global__ __launch_bounds__(192) void filter_kernel(const float* __restrict__ sino) {
    __shared__ float2 s_h2p[368];      // 736 floats
    __shared__ float2 s_row2[184];     // 368 floats; [363..367] = 0
    __shared__ float  s_out[546];      // full padded row (zeros in pads)
    float* s_h2  = (float*)s_h2p;
    float* s_row = (float*)s_row2;

    int t   = threadIdx.x;             // 0..191
    int row = blockIdx.x;              // 0..719

    if (t < 184)
        ((float4*)s_h2)[t] = ((const float4*)g_h2)[t];
    for (int i = t; i < 368; i += 192)
        s_row[i] = (i < D_DET) ? __ldg(sino + row * D_DET + i) : 0.0f;
    for (int i = t; i < 546; i += 192) s_out[i] = 0.0f;
    __syncthreads();

    // ---- convolution: outputs d0, d0+1; h window slides 2 per double-step ----
    if (t < 182) {
        int d0   = 2 * t;                        // 0..362
        int base = 366 + d0;                     // even -> float2-aligned pairs
        float w0 = s_h2[base];
        float w1 = s_h2[base + 1];
        int hb2  = (base - 2) >> 1;              // float2 index of s_h2[base-2]
        float a0 = 0.f, a1 = 0.f;
        #pragma unroll 4
        for (int k2 = 0; k2 < 182; k2++) {       // k = 2*k2, 2*k2+1 (s_row[363]=0)
            float2 sv = s_row2[k2];              // broadcast across warp
            float2 hp = s_h2p[hb2 - k2];         // (h[base-2-2k2], h[base-1-2k2])
            a0 = fmaf(sv.x, w0, a0);
            a1 = fmaf(sv.x, w1, a1);
            a0 = fmaf(sv.y, hp.y, a0);
            a1 = fmaf(sv.y, w0, a1);
            w1 = hp.y; w0 = hp.x;
        }
        s_out[PAD + d0] = a0;
        if (d0 + 1 < D_DET) s_out[PAD + d0 + 1] = a1;
    }
    __syncthreads();

    // ---- write delta-packed padded row, pre-scaled by pi/360 ----
    const float SC = (float)(M_PI / 360.0);
    for (int i = t; i < SROW; i += 192) {
        float v0 = s_out[i];
        g_filt2[row * SROW + i] = make_float2(v0 * SC, (s_out[i + 1] - v0) * SC);
    }
}

// ============================================================================
// Kernel 2: backprojection (R14-proven inner loop). 16x16 tile; z = angle
// quarter (90 angles/chain); both batches per thread (shared u/floor/address,
// 2nd LDG via immediate offset). Quarter-partials accumulated straight into
// d_out with atomicAdd (combine kernel eliminated).
// ============================================================================
__global__ __launch_bounds__(256) void bp_kernel(float* __restrict__ out) {
    __shared__ float2 s_trig[QTR_A];
    int tid = threadIdx.y * 16 + threadIdx.x;
    int q = blockIdx.z;                // angle quarter
    int a0 = q * QTR_A;

    const float C1 = 32761.0f / (127.5f * 1.41421356237309515f);  // 181^2/(127.5*sqrt2)
    if (tid < QTR_A) {
        float sa, ca;
        sincospif((float)(a0 + tid) * (1.0f / 360.0f), &sa, &ca); // angle = idx*pi/360
        s_trig[tid] = make_float2(ca * C1, sa * C1);
    }
    __syncthreads();

    int x = blockIdx.x * 16 + threadIdx.x;
    int y = blockIdx.y * 16 + threadIdx.y;
    float xf = fmaf((float)x, 2.0f / 255.0f, -1.0f);
    float yf = fmaf((float)y, 2.0f / 255.0f, -1.0f);

    const float2* p = g_filt2 + a0 * SROW;
    float accA = 0.0f, accB = 0.0f;
    #pragma unroll 5
    for (int a = 0; a < QTR_A; a++) {
        float2 cs = s_trig[a];
        float u  = fmaf(xf, cs.x, fmaf(yf, cs.y, 257.0f));  // 257 = PAD + (D-1)/2
        int   i0 = __float2int_rd(u);                       // u > 0: exact floor
        float w  = u - (float)i0;
        float2 vA = __ldg(p + i0);
        float2 vB = __ldg(p + i0 + BATCH_OFF);              // immediate offset
        accA = fmaf(w, vA.y, accA + vA.x);                  // f0 + w*(f1-f0)
        accB = fmaf(w, vB.y, accB + vB.x);
        p += SROW;
    }

    int pix = y * IMG + x;
    atomicAdd(out + pix,             accA);
    atomicAdd(out + IMG * IMG + pix, accB);
}

// ============================================================================
extern "C" void kernel_launch(void* const* d_in, const int* in_sizes, int n_in,
                              void* d_out, int out_size) {
    const float* sino = (const float*)d_in[0];   // (2,1,360,363) float32
    float* out = (float*)d_out;                  // (2,1,256,256) float32

    prep_kernel<<<128, 256>>>(out);
    filter_kernel<<<NROWS, 192>>>(sino);
    bp_kernel<<<dim3(IMG / 16, IMG / 16, 4), dim3(16, 16)>>>(out);
}